// round 15
// baseline (speedup 1.0000x reference)
#include <cuda_runtime.h>
#include <cuda_bf16.h>
#include <cuda_fp16.h>
#include <math.h>
#include <stdint.h>

// Problem constants
#define Bn   64
#define Ln   512
#define En   300
#define Vv   50000
#define Pn   200
#define Dn   2800          // P * 2 * M
#define Hn   100
#define Mtot (Bn * Ln)     // 32768
#define NEG  (-100.0f)
#define NINF (-1.0e30f)

// GEMM config: plain fp16 GEMM, K padded 300->320.
#define Kp    320
#define Np    2816
#define TM    128
#define TN    128
#define BK    32                 // fp16 per k-tile
#define NKT   10                 // 10 chunks (chunk 9: ks=0 only; k 304+ zero)
#define ROWB  80u                // padded smem row stride (bytes) per 32-fp16 row
#define ASZ   (128u * ROWB)      // 10240
#define STAGE (2u * ASZ)         // A + B = 20480
#define NSTG  3
#define SMEM_DYN (NSTG * STAGE)  // 61440

// Scan split config
#define NCH   4
#define CL    (Ln / NCH)         // 128

// Scratch (static device globals — no dynamic allocation; zero-initialized)
__device__ __align__(256) __half g_tsu[(size_t)Mtot * Np];  // [uid][n] fp16
__device__ __align__(256) float  g_part[(size_t)Bn * Pn * NCH * 64];
__device__ __align__(256) __half g_A2[(size_t)Mtot * Kp];   // fp16(a)
__device__ __align__(256) __half g_B2[(size_t)Np * Kp];     // fp16(b)
__device__ int g_flag[Vv];       // 0 outside a launch; uid+1 during
__device__ int g_tok[Mtot];
__device__ int g_count;

// ---------------------------------------------------------------------------
// PTX helpers (baseline PTX only — no 'a'-target instructions)
// ---------------------------------------------------------------------------
__device__ __forceinline__ uint32_t s2u(const void* p) {
    uint32_t a;
    asm("{ .reg .u64 t; cvta.to.shared.u64 t, %1; cvt.u32.u64 %0, t; }"
        : "=r"(a) : "l"(p));
    return a;
}

#define CP_ASYNC16(dst, src) \
    asm volatile("cp.async.cg.shared.global [%0], [%1], 16;" :: "r"(dst), "l"(src) : "memory")
#define CP_COMMIT() asm volatile("cp.async.commit_group;" ::: "memory")
#define CP_WAIT(n)  asm volatile("cp.async.wait_group %0;" :: "n"(n) : "memory")

#define LDSM_X4(r, addr)                                                        \
    asm volatile("ldmatrix.sync.aligned.m8n8.x4.shared.b16 {%0,%1,%2,%3}, [%4];" \
        : "=r"((r)[0]), "=r"((r)[1]), "=r"((r)[2]), "=r"((r)[3]) : "r"(addr))

#define LDSM_X4_B(r0, r1, r2, r3, addr)                                         \
    asm volatile("ldmatrix.sync.aligned.m8n8.x4.shared.b16 {%0,%1,%2,%3}, [%4];" \
        : "=r"(r0), "=r"(r1), "=r"(r2), "=r"(r3) : "r"(addr))

#define MMA_F16(d, a, b)                                                        \
    asm volatile("mma.sync.aligned.m16n8k16.row.col.f32.f16.f16.f32 "           \
        "{%0,%1,%2,%3}, {%4,%5,%6,%7}, {%8,%9}, {%0,%1,%2,%3};"                 \
        : "+f"((d)[0]), "+f"((d)[1]), "+f"((d)[2]), "+f"((d)[3])                \
        : "r"((a)[0]), "r"((a)[1]), "r"((a)[2]), "r"((a)[3]),                   \
          "r"((b)[0]), "r"((b)[1]))

// ---------------------------------------------------------------------------
// Dedup. Flags are zero at entry (static init / tail unmark restores them).
// ---------------------------------------------------------------------------
__global__ void dedup_mark_kernel(const int* __restrict__ docs) {
    const int m = blockIdx.x * blockDim.x + threadIdx.x;
    if (m < Mtot) g_flag[docs[m]] = 1;       // racing writes of 1: benign
}
__global__ void __launch_bounds__(1024) dedup_scan_kernel() {
    __shared__ int ss[1024];
    const int tid = threadIdx.x;
    const int CHUNK = (Vv + 1023) / 1024;    // 49
    const int base = tid * CHUNK;
    int s = 0;
    for (int i = 0; i < CHUNK; i++) {
        const int v = base + i;
        if (v < Vv) s += g_flag[v];
    }
    ss[tid] = s;
    __syncthreads();
    for (int off = 1; off < 1024; off <<= 1) {
        int v = (tid >= off) ? ss[tid - off] : 0;
        __syncthreads();
        ss[tid] += v;
        __syncthreads();
    }
    int run = (tid == 0) ? 0 : ss[tid - 1];
    if (tid == 1023) g_count = ss[1023];
    for (int i = 0; i < CHUNK; i++) {
        const int v = base + i;
        if (v < Vv && g_flag[v]) {
            g_tok[run] = v;
            g_flag[v] = run + 1;             // uid+1 (0 = unused)
            run++;
        }
    }
}
// Tail kernel: restore flags to 0 for the next graph replay (deterministic).
__global__ void dedup_unmark_kernel() {
    const int i = blockIdx.x * blockDim.x + threadIdx.x;
    if (i < g_count) g_flag[g_tok[i]] = 0;
}

// ---------------------------------------------------------------------------
// Conversion (merged): blocks [0, Mtot) -> A rows (gathered, early exit),
// blocks [Mtot, Mtot+Np) -> B rows.
// ---------------------------------------------------------------------------
__global__ void conv_all_kernel(const float* __restrict__ emb,
                                const float* __restrict__ diags)
{
    const int blk = blockIdx.x;
    const int k = threadIdx.x;          // 0..319
    if (blk < Mtot) {
        if (blk >= g_count) return;
        const int tok = g_tok[blk];
        float x = (k < En) ? emb[(size_t)tok * En + k] : 0.0f;
        g_A2[(size_t)blk * Kp + k] = __float2half_rn(x);
    } else {
        const int d = blk - Mtot;       // 0..2815
        float x = (d < Dn && k < En) ? diags[(size_t)d * En + k] : 0.0f;
        g_B2[(size_t)d * Kp + k] = __float2half_rn(x);
    }
}

// ---------------------------------------------------------------------------
// Kernel: fp16 HMMA GEMM over uid rows.  ts_u[u,n] = A2[u]·B2[n] + bias[n]
// Chunk 9 covers k 288..319; cols 304..319 are zero -> ks=1 skipped.
// ---------------------------------------------------------------------------
__global__ void __launch_bounds__(256, 2)
gemm_hmma_kernel(const float* __restrict__ bias)
{
    const int m0 = blockIdx.y * TM;
    const int cnt = g_count;
    if (m0 >= cnt) return;              // uniform per-CTA exit

    extern __shared__ char smem[];
    const uint32_t sbase = s2u(smem);

    const int tid  = threadIdx.x;
    const int wid  = tid >> 5;
    const int lane = tid & 31;
    const int wm   = wid & 3;            // 0..3  (M)
    const int wn   = wid >> 2;           // 0..1  (N)
    const int n0   = blockIdx.x * TN;

    const uint32_t aoff = (uint32_t)((((lane >> 3) & 1) * 8 + (lane & 7)) * ROWB
                                     + ((lane >> 4) * 8) * 2);
    const uint32_t boff = (uint32_t)(((lane >> 4) * 8 + (lane & 7)) * ROWB
                                     + (((lane >> 3) & 1) * 8) * 2);

    const int cr0 = tid >> 2;            // rows 0..63 (+64)
    const int cc  = (tid & 3) * 8;       // fp16 col offset

    auto load_stage = [&](int buf, int kt) {
        const uint32_t sb = sbase + (uint32_t)buf * STAGE;
        const int kk = kt * BK;
        const bool used = (kt != 9) || (cc < 16);   // cols 304+ never consumed
        if (used) {
            #pragma unroll
            for (int u = 0; u < 2; u++) {
                const int r = cr0 + u * 64;
                CP_ASYNC16(sb + (uint32_t)r * ROWB + (uint32_t)(cc * 2),
                           g_A2 + (size_t)(m0 + r) * Kp + kk + cc);
            }
            #pragma unroll
            for (int u = 0; u < 2; u++) {
                const int r = cr0 + u * 64;
                CP_ASYNC16(sb + ASZ + (uint32_t)r * ROWB + (uint32_t)(cc * 2),
                           g_B2 + (size_t)(n0 + r) * Kp + kk + cc);
            }
        }
        CP_COMMIT();
    };

    float c[2][8][4];
    #pragma unroll
    for (int i = 0; i < 2; i++)
        #pragma unroll
        for (int j = 0; j < 8; j++)
            #pragma unroll
            for (int q = 0; q < 4; q++) c[i][j][q] = 0.f;

    load_stage(0, 0);
    load_stage(1, 1);

    for (int kt = 0; kt < NKT; kt++) {
        if (kt < NKT - 1) CP_WAIT(1);
        else              CP_WAIT(0);
        __syncthreads();

        if (kt + 2 < NKT) load_stage((kt + 2) % NSTG, kt + 2);

        const uint32_t sA = sbase + (uint32_t)(kt % NSTG) * STAGE;
        const uint32_t sB = sA + ASZ;

        auto do_ks = [&](int ks) {
            uint32_t a[2][4], bfr[8][2];
            #pragma unroll
            for (int i = 0; i < 2; i++)
                LDSM_X4(a[i], sA + (uint32_t)((wm * 32 + i * 16) * ROWB) + (uint32_t)(ks * 32) + aoff);
            #pragma unroll
            for (int j2 = 0; j2 < 4; j2++)
                LDSM_X4_B(bfr[j2 * 2][0], bfr[j2 * 2][1],
                          bfr[j2 * 2 + 1][0], bfr[j2 * 2 + 1][1],
                          sB + (uint32_t)((wn * 64 + j2 * 16) * ROWB) + (uint32_t)(ks * 32) + boff);
            #pragma unroll
            for (int i = 0; i < 2; i++)
                #pragma unroll
                for (int j = 0; j < 8; j++)
                    MMA_F16(c[i][j], a[i], bfr[j]);
        };

        do_ks(0);
        if (kt != 9) do_ks(1);            // tail chunk: k 304..319 are all zero
    }

    // ---- epilogue: fp16 [uid][n] store with bias ----
    const int gid = lane >> 2;
    const int tig = lane & 3;
    #pragma unroll
    for (int i = 0; i < 2; i++) {
        const int r0 = m0 + wm * 32 + i * 16 + gid;
        #pragma unroll
        for (int j = 0; j < 8; j++) {
            const int n = n0 + wn * 64 + j * 8 + tig * 2;
            const float bx = __ldg(bias + (n < Dn ? n : 0));
            const float by = __ldg(bias + (n + 1 < Dn ? n + 1 : 0));
            #pragma unroll
            for (int h = 0; h < 2; h++) {
                const int m = r0 + h * 8;
                if (m < cnt) {
                    __half2 v = __floats2half2_rn(c[i][j][h * 2] + bx,
                                                  c[i][j][h * 2 + 1] + by);
                    *reinterpret_cast<__half2*>(g_tsu + (size_t)m * Np + n) = v;
                }
            }
        }
    }
}

// ---------------------------------------------------------------------------
// Scan: max-plus affine chunk transform, columns SPLIT across blockIdx.z:
//   z=0: basis columns 0..2 (18 positions)
//   z=1: basis columns 3..6 + const column (17 positions)
// Lower register pressure -> 3 CTAs/SM (24 warps) vs previous 16.
// Slot layout (64 floats): [0..48] M cols j*7+i, [49..55] C, [56..63] S.
// ---------------------------------------------------------------------------
template<int J0, int J1, bool DOCONST>
__device__ __forceinline__ void scan_cols(const int* __restrict__ uids,
                                          const float* __restrict__ epsilon,
                                          int b, int ch, int p)
{
    constexpr int NC = J1 - J0;

    float e[6];
    #pragma unroll
    for (int j = 0; j < 6; j++) e[j] = __ldg(epsilon + p * 6 + j);

    float h[NC][7];
    #pragma unroll
    for (int jj = 0; jj < NC; jj++) {
        #pragma unroll
        for (int i = 0; i < 7; i++) h[jj][i] = NINF;
        h[jj][J0 + jj] = 0.0f;
    }
    float smax[NC];
    #pragma unroll
    for (int jj = 0; jj < NC; jj++) smax[jj] = NINF;

    float hc[7];
    float smaxc = NINF;
    if (DOCONST) {
        #pragma unroll
        for (int i = 0; i < 7; i++) hc[i] = NINF;
    }

    const int poff7 = p * 7;   // half2 units

    float2 nxv[7];
    {
        const __half2* r = reinterpret_cast<const __half2*>(
            g_tsu + (size_t)uids[0] * Np) + poff7;
        #pragma unroll
        for (int q = 0; q < 7; q++) nxv[q] = __half22float2(r[q]);
    }

    for (int l = 0; l < CL; l++) {
        float xv[14];
        #pragma unroll
        for (int q = 0; q < 7; q++) { xv[2 * q] = nxv[q].x; xv[2 * q + 1] = nxv[q].y; }
        if (l + 1 < CL) {
            const __half2* r = reinterpret_cast<const __half2*>(
                g_tsu + (size_t)uids[l + 1] * Np) + poff7;
            #pragma unroll
            for (int q = 0; q < 7; q++) nxv[q] = __half22float2(r[q]);
        }

        #pragma unroll
        for (int jj = 0; jj < NC; jj++) {
            constexpr int dummy = 0; (void)dummy;
            const int j = J0 + jj;
            float nh[7];
            float aeprev = h[jj][j];                // ae[j]
            nh[j] = aeprev + xv[j];                 // pure self-loop at state j
            #pragma unroll
            for (int m = J0 + jj + 1; m < 7; m++) {
                const float aem = fmaxf(h[jj][m], h[jj][m - 1] + e[m - 1]);
                nh[m] = fmaxf(aeprev + xv[7 + m - 1], aem + xv[m]);
                aeprev = aem;
            }
            smax[jj] = fmaxf(smax[jj], nh[6]);
            #pragma unroll
            for (int m = J0 + jj; m < 7; m++) h[jj][m] = nh[m];
        }

        if (DOCONST) {
            float ae[7];
            ae[0] = fmaxf(hc[0], NEG);
            #pragma unroll
            for (int m = 1; m < 7; m++) ae[m] = fmaxf(hc[m], hc[m - 1] + e[m - 1]);
            float nh[7];
            nh[0] = fmaxf(0.0f, ae[0] + xv[0]);
            #pragma unroll
            for (int m = 1; m < 7; m++)
                nh[m] = fmaxf(ae[m - 1] + xv[7 + m - 1], ae[m] + xv[m]);
            smaxc = fmaxf(smaxc, nh[6]);
            #pragma unroll
            for (int m = 0; m < 7; m++) hc[m] = nh[m];
        }
    }

    float* slot = g_part + ((size_t)(b * Pn + p) * NCH + ch) * 64;
    #pragma unroll
    for (int jj = 0; jj < NC; jj++) {
        const int j = J0 + jj;
        #pragma unroll
        for (int i = 0; i < 7; i++)
            slot[j * 7 + i] = (i >= j) ? h[jj][i] : NINF;
        slot[56 + j] = smax[jj];
    }
    if (DOCONST) {
        #pragma unroll
        for (int i = 0; i < 7; i++) slot[49 + i] = hc[i];
        slot[63] = smaxc;
    }
}

__global__ void __launch_bounds__(256, 3)
scan_part_kernel(const int* __restrict__ docs,
                 const float* __restrict__ epsilon)
{
    const int b   = blockIdx.x;
    const int ch  = blockIdx.y;
    const int tid = threadIdx.x;

    __shared__ int uids[CL];
    if (tid < CL)
        uids[tid] = g_flag[docs[b * Ln + ch * CL + tid]] - 1;
    __syncthreads();
    if (tid >= Pn) return;

    if (blockIdx.z == 0) scan_cols<0, 3, false>(uids, epsilon, b, ch, tid);
    else                 scan_cols<3, 7, true >(uids, epsilon, b, ch, tid);
}

// ---------------------------------------------------------------------------
// Fused combine + MLP + log_softmax. One block per batch row.
// ---------------------------------------------------------------------------
__global__ void __launch_bounds__(256)
mlp_kernel(const float* __restrict__ w1, const float* __restrict__ b1,
           const float* __restrict__ w2, const float* __restrict__ b2,
           const float* __restrict__ w3, const float* __restrict__ b3,
           float* __restrict__ out)
{
    const int b = blockIdx.x;
    const int tid = threadIdx.x;
    __shared__ float sc[Pn];
    __shared__ float h1[Hn];
    __shared__ float h2[Hn];

    if (tid < Pn) {
        float h[7];
        h[0] = 0.0f;
        #pragma unroll
        for (int i = 1; i < 7; i++) h[i] = NEG;
        float s = NEG;
        #pragma unroll 1
        for (int c = 0; c < NCH; c++) {
            const float* sl = g_part + ((size_t)(b * Pn + tid) * NCH + c) * 64;
            float ns = fmaxf(s, sl[63]);
            #pragma unroll
            for (int j = 0; j < 7; j++) ns = fmaxf(ns, sl[56 + j] + h[j]);
            float nh[7];
            #pragma unroll
            for (int i = 0; i < 7; i++) {
                float v = sl[49 + i];
                #pragma unroll
                for (int j = 0; j < 7; j++) v = fmaxf(v, sl[j * 7 + i] + h[j]);
                nh[i] = v;
            }
            #pragma unroll
            for (int i = 0; i < 7; i++) h[i] = nh[i];
            s = ns;
        }
        sc[tid] = s;
    }
    __syncthreads();

    if (tid < Hn) {
        float acc = b1[tid];
        #pragma unroll 4
        for (int p = 0; p < Pn; p++) acc = fmaf(sc[p], w1[p * Hn + tid], acc);
        h1[tid] = fmaxf(acc, 0.f);
    }
    __syncthreads();

    if (tid < Hn) {
        float acc = b2[tid];
        #pragma unroll 4
        for (int j = 0; j < Hn; j++) acc = fmaf(h1[j], w2[j * Hn + tid], acc);
        h2[tid] = fmaxf(acc, 0.f);
    }
    __syncthreads();

    if (tid == 0) {
        float l0 = b3[0], l1 = b3[1];
        for (int j = 0; j < Hn; j++) {
            l0 = fmaf(h2[j], w3[j * 2 + 0], l0);
            l1 = fmaf(h2[j], w3[j * 2 + 1], l1);
        }
        float mx  = fmaxf(l0, l1);
        float lse = mx + logf(expf(l0 - mx) + expf(l1 - mx));
        out[b * 2 + 0] = l0 - lse;
        out[b * 2 + 1] = l1 - lse;
    }
}

// ---------------------------------------------------------------------------
extern "C" void kernel_launch(void* const* d_in, const int* in_sizes, int n_in,
                              void* d_out, int out_size)
{
    const int*   docs    = (const int*)  d_in[0];
    const float* emb     = (const float*)d_in[1];
    const float* diags   = (const float*)d_in[2];
    const float* bias    = (const float*)d_in[3];
    const float* epsilon = (const float*)d_in[4];
    const float* w1      = (const float*)d_in[5];
    const float* b1      = (const float*)d_in[6];
    const float* w2      = (const float*)d_in[7];
    const float* b2      = (const float*)d_in[8];
    const float* w3      = (const float*)d_in[9];
    const float* b3      = (const float*)d_in[10];
    float* out = (float*)d_out;

    cudaFuncSetAttribute(gemm_hmma_kernel,
                         cudaFuncAttributeMaxDynamicSharedMemorySize, SMEM_DYN);

    // 0: mark (flags are zero at entry; restored by unmark below)
    dedup_mark_kernel<<<(Mtot + 255) / 256, 256>>>(docs);
    // 1: prefix scan -> g_tok, g_count, flags = uid+1
    dedup_scan_kernel<<<1, 1024>>>();
    // 2: conversions (A gathered via g_tok, B direct)
    conv_all_kernel<<<Mtot + Np, Kp>>>(emb, diags);
    // 3: GEMM (profiled launch index)
    dim3 gridG(Np / TN, Mtot / TM);   // (22, 256); CTAs beyond count exit
    gemm_hmma_kernel<<<gridG, 256, SMEM_DYN>>>(bias);
    // 4: scan (uid lookup inline via flags)
    dim3 gridS(Bn, NCH, 2);           // (64, 4, 2)
    scan_part_kernel<<<gridS, 256>>>(docs, epsilon);
    // 5: fused combine + MLP
    mlp_kernel<<<Bn, 256>>>(w1, b1, w2, b2, w3, b3, out);
    // 6: restore flags to zero for next replay
    dedup_unmark_kernel<<<(Mtot + 255) / 256, 256>>>();
}

// round 16
// speedup vs baseline: 1.1774x; 1.1774x over previous
#include <cuda_runtime.h>
#include <cuda_bf16.h>
#include <cuda_fp16.h>
#include <math.h>
#include <stdint.h>

// Problem constants
#define Bn   64
#define Ln   512
#define En   300
#define Vv   50000
#define Pn   200
#define Dn   2800          // P * 2 * M
#define Hn   100
#define Mtot (Bn * Ln)     // 32768
#define NEG  (-100.0f)
#define NINF (-1.0e30f)

// GEMM config: plain fp16 GEMM, K padded 300->320, BK=64 chunks.
#define Kp    320
#define Np    2816
#define TM    128
#define TN    128
#define BK    64                 // fp16 per k-chunk (4 k-steps of 16)
#define NKT   5                  // 5 chunks (chunk 4: ks=3 skipped; k 304+ zero)
#define ROWB  144u               // smem row stride: 128B data + 16B pad
#define ASZ   (128u * ROWB)      // 18432
#define STAGE (2u * ASZ)         // A + B = 36864
#define NSTG  3
#define SMEM_DYN (NSTG * STAGE)  // 110592 (2 CTAs/SM = 221KB, fits 228KB)

// Scan split config
#define NCH   4
#define CL    (Ln / NCH)         // 128

// Scratch (static device globals — no dynamic allocation; zero-initialized)
__device__ __align__(256) __half g_tsu[(size_t)Mtot * Np];  // [uid][n] fp16
__device__ __align__(256) float  g_part[(size_t)Bn * Pn * NCH * 64];
__device__ __align__(256) __half g_A2[(size_t)Mtot * Kp];   // fp16(a)
__device__ __align__(256) __half g_B2[(size_t)Np * Kp];     // fp16(b)
__device__ int g_flag[Vv];       // 0 outside a launch; uid+1 during
__device__ int g_tok[Mtot];
__device__ int g_count;

// ---------------------------------------------------------------------------
// PTX helpers (baseline PTX only — no 'a'-target instructions)
// ---------------------------------------------------------------------------
__device__ __forceinline__ uint32_t s2u(const void* p) {
    uint32_t a;
    asm("{ .reg .u64 t; cvta.to.shared.u64 t, %1; cvt.u32.u64 %0, t; }"
        : "=r"(a) : "l"(p));
    return a;
}

#define CP_ASYNC16(dst, src) \
    asm volatile("cp.async.cg.shared.global [%0], [%1], 16;" :: "r"(dst), "l"(src) : "memory")
#define CP_COMMIT() asm volatile("cp.async.commit_group;" ::: "memory")
#define CP_WAIT(n)  asm volatile("cp.async.wait_group %0;" :: "n"(n) : "memory")

#define LDSM_X4(r, addr)                                                        \
    asm volatile("ldmatrix.sync.aligned.m8n8.x4.shared.b16 {%0,%1,%2,%3}, [%4];" \
        : "=r"((r)[0]), "=r"((r)[1]), "=r"((r)[2]), "=r"((r)[3]) : "r"(addr))

#define LDSM_X4_B(r0, r1, r2, r3, addr)                                         \
    asm volatile("ldmatrix.sync.aligned.m8n8.x4.shared.b16 {%0,%1,%2,%3}, [%4];" \
        : "=r"(r0), "=r"(r1), "=r"(r2), "=r"(r3) : "r"(addr))

#define MMA_F16(d, a, b)                                                        \
    asm volatile("mma.sync.aligned.m16n8k16.row.col.f32.f16.f16.f32 "           \
        "{%0,%1,%2,%3}, {%4,%5,%6,%7}, {%8,%9}, {%0,%1,%2,%3};"                 \
        : "+f"((d)[0]), "+f"((d)[1]), "+f"((d)[2]), "+f"((d)[3])                \
        : "r"((a)[0]), "r"((a)[1]), "r"((a)[2]), "r"((a)[3]),                   \
          "r"((b)[0]), "r"((b)[1]))

// ---------------------------------------------------------------------------
// Dedup. Flags are zero at entry (static init / tail unmark restores them).
// ---------------------------------------------------------------------------
__global__ void dedup_mark_kernel(const int* __restrict__ docs) {
    const int m = blockIdx.x * blockDim.x + threadIdx.x;
    if (m < Mtot) g_flag[docs[m]] = 1;       // racing writes of 1: benign
}
__global__ void __launch_bounds__(1024) dedup_scan_kernel() {
    __shared__ int ss[1024];
    const int tid = threadIdx.x;
    const int CHUNK = (Vv + 1023) / 1024;    // 49
    const int base = tid * CHUNK;
    int s = 0;
    for (int i = 0; i < CHUNK; i++) {
        const int v = base + i;
        if (v < Vv) s += g_flag[v];
    }
    ss[tid] = s;
    __syncthreads();
    for (int off = 1; off < 1024; off <<= 1) {
        int v = (tid >= off) ? ss[tid - off] : 0;
        __syncthreads();
        ss[tid] += v;
        __syncthreads();
    }
    int run = (tid == 0) ? 0 : ss[tid - 1];
    if (tid == 1023) g_count = ss[1023];
    for (int i = 0; i < CHUNK; i++) {
        const int v = base + i;
        if (v < Vv && g_flag[v]) {
            g_tok[run] = v;
            g_flag[v] = run + 1;             // uid+1 (0 = unused)
            run++;
        }
    }
}
// Tail kernel: restore flags to 0 for the next graph replay (deterministic).
__global__ void dedup_unmark_kernel() {
    const int i = blockIdx.x * blockDim.x + threadIdx.x;
    if (i < g_count) g_flag[g_tok[i]] = 0;
}

// ---------------------------------------------------------------------------
// Conversion (merged): blocks [0, Mtot) -> A rows (gathered, early exit),
// blocks [Mtot, Mtot+Np) -> B rows.
// ---------------------------------------------------------------------------
__global__ void conv_all_kernel(const float* __restrict__ emb,
                                const float* __restrict__ diags)
{
    const int blk = blockIdx.x;
    const int k = threadIdx.x;          // 0..319
    if (blk < Mtot) {
        if (blk >= g_count) return;
        const int tok = g_tok[blk];
        float x = (k < En) ? emb[(size_t)tok * En + k] : 0.0f;
        g_A2[(size_t)blk * Kp + k] = __float2half_rn(x);
    } else {
        const int d = blk - Mtot;       // 0..2815
        float x = (d < Dn && k < En) ? diags[(size_t)d * En + k] : 0.0f;
        g_B2[(size_t)d * Kp + k] = __float2half_rn(x);
    }
}

// ---------------------------------------------------------------------------
// Kernel: fp16 HMMA GEMM over uid rows.  ts_u[u,n] = A2[u]·B2[n] + bias[n]
// BK=64 chunks, 3-stage cp.async, 5 __syncthreads total.
// Chunk 4 covers k 256..319; cols 304..319 are zero -> ks=3 skipped.
// ---------------------------------------------------------------------------
__global__ void __launch_bounds__(256, 2)
gemm_hmma_kernel(const float* __restrict__ bias)
{
    const int m0 = blockIdx.y * TM;
    const int cnt = g_count;
    if (m0 >= cnt) return;              // uniform per-CTA exit

    extern __shared__ char smem[];
    const uint32_t sbase = s2u(smem);

    const int tid  = threadIdx.x;
    const int wid  = tid >> 5;
    const int lane = tid & 31;
    const int wm   = wid & 3;            // 0..3  (M)
    const int wn   = wid >> 2;           // 0..1  (N)
    const int n0   = blockIdx.x * TN;

    const uint32_t aoff = (uint32_t)((((lane >> 3) & 1) * 8 + (lane & 7)) * ROWB
                                     + ((lane >> 4) * 8) * 2);
    const uint32_t boff = (uint32_t)(((lane >> 4) * 8 + (lane & 7)) * ROWB
                                     + (((lane >> 3) & 1) * 8) * 2);

    // cp.async: 1024 16B chunks for A + 1024 for B per stage; 4+4 per thread
    auto load_stage = [&](int buf, int kt) {
        const uint32_t sb = sbase + (uint32_t)buf * STAGE;
        const int k0 = kt * BK;
        #pragma unroll
        for (int i = 0; i < 4; i++) {
            const int c   = tid + i * 256;       // 0..1023
            const int row = c >> 3;
            const int ce  = (c & 7) * 8;         // fp16 element col 0..56
            const bool used = (kt != 4) || (ce < 48);   // k 304+ never consumed
            if (used) {
                CP_ASYNC16(sb + (uint32_t)row * ROWB + (uint32_t)(ce * 2),
                           g_A2 + (size_t)(m0 + row) * Kp + k0 + ce);
                CP_ASYNC16(sb + ASZ + (uint32_t)row * ROWB + (uint32_t)(ce * 2),
                           g_B2 + (size_t)(n0 + row) * Kp + k0 + ce);
            }
        }
        CP_COMMIT();
    };

    float c[2][8][4];
    #pragma unroll
    for (int i = 0; i < 2; i++)
        #pragma unroll
        for (int j = 0; j < 8; j++)
            #pragma unroll
            for (int q = 0; q < 4; q++) c[i][j][q] = 0.f;

    load_stage(0, 0);
    load_stage(1, 1);

    for (int kt = 0; kt < NKT; kt++) {
        if (kt < NKT - 1) CP_WAIT(1);
        else              CP_WAIT(0);
        __syncthreads();

        if (kt + 2 < NKT) load_stage((kt + 2) % NSTG, kt + 2);

        const uint32_t sA = sbase + (uint32_t)(kt % NSTG) * STAGE;
        const uint32_t sB = sA + ASZ;

        auto do_ks = [&](int ks) {
            uint32_t a[2][4], bfr[8][2];
            #pragma unroll
            for (int i = 0; i < 2; i++)
                LDSM_X4(a[i], sA + (uint32_t)((wm * 32 + i * 16) * ROWB) + (uint32_t)(ks * 32) + aoff);
            #pragma unroll
            for (int j2 = 0; j2 < 4; j2++)
                LDSM_X4_B(bfr[j2 * 2][0], bfr[j2 * 2][1],
                          bfr[j2 * 2 + 1][0], bfr[j2 * 2 + 1][1],
                          sB + (uint32_t)((wn * 64 + j2 * 16) * ROWB) + (uint32_t)(ks * 32) + boff);
            #pragma unroll
            for (int i = 0; i < 2; i++)
                #pragma unroll
                for (int j = 0; j < 8; j++)
                    MMA_F16(c[i][j], a[i], bfr[j]);
        };

        do_ks(0);
        do_ks(1);
        do_ks(2);
        if (kt != 4) do_ks(3);            // tail chunk: k 304..319 are all zero
    }

    // ---- epilogue: fp16 [uid][n] store with bias ----
    const int gid = lane >> 2;
    const int tig = lane & 3;
    #pragma unroll
    for (int i = 0; i < 2; i++) {
        const int r0 = m0 + wm * 32 + i * 16 + gid;
        #pragma unroll
        for (int j = 0; j < 8; j++) {
            const int n = n0 + wn * 64 + j * 8 + tig * 2;
            const float bx = __ldg(bias + (n < Dn ? n : 0));
            const float by = __ldg(bias + (n + 1 < Dn ? n + 1 : 0));
            #pragma unroll
            for (int h = 0; h < 2; h++) {
                const int m = r0 + h * 8;
                if (m < cnt) {
                    __half2 v = __floats2half2_rn(c[i][j][h * 2] + bx,
                                                  c[i][j][h * 2 + 1] + by);
                    *reinterpret_cast<__half2*>(g_tsu + (size_t)m * Np + n) = v;
                }
            }
        }
    }
}

// ---------------------------------------------------------------------------
// Scan: chunked max-plus affine transform; one thread = all 8 columns;
// each ts row read ONCE per (b,ch) block. Triangular basis.
// Slot layout (64 floats): [0..48] M cols j*7+i, [49..55] C, [56..63] S.
// ---------------------------------------------------------------------------
__global__ void __launch_bounds__(256)
scan_part_kernel(const int* __restrict__ docs,
                 const float* __restrict__ epsilon)
{
    const int b   = blockIdx.x;
    const int ch  = blockIdx.y;
    const int tid = threadIdx.x;

    __shared__ int uids[CL];
    if (tid < CL)
        uids[tid] = g_flag[docs[b * Ln + ch * CL + tid]] - 1;
    __syncthreads();
    if (tid >= Pn) return;
    const int p = tid;

    float e[6];
    #pragma unroll
    for (int j = 0; j < 6; j++) e[j] = __ldg(epsilon + p * 6 + j);

    float h[8][7];
    #pragma unroll
    for (int j = 0; j < 8; j++)
        #pragma unroll
        for (int i = 0; i < 7; i++) h[j][i] = NINF;
    #pragma unroll
    for (int j = 0; j < 7; j++) h[j][j] = 0.0f;
    float smax[8];
    #pragma unroll
    for (int j = 0; j < 8; j++) smax[j] = NINF;

    const int poff7 = p * 7;   // half2 units

    float2 nxv[7];
    {
        const __half2* r = reinterpret_cast<const __half2*>(
            g_tsu + (size_t)uids[0] * Np) + poff7;
        #pragma unroll
        for (int q = 0; q < 7; q++) nxv[q] = __half22float2(r[q]);
    }

    for (int l = 0; l < CL; l++) {
        float xv[14];
        #pragma unroll
        for (int q = 0; q < 7; q++) { xv[2 * q] = nxv[q].x; xv[2 * q + 1] = nxv[q].y; }
        if (l + 1 < CL) {
            const __half2* r = reinterpret_cast<const __half2*>(
                g_tsu + (size_t)uids[l + 1] * Np) + poff7;
            #pragma unroll
            for (int q = 0; q < 7; q++) nxv[q] = __half22float2(r[q]);
        }

        // basis columns j = 0..6 (triangular: states < j stay NINF)
        #pragma unroll
        for (int j = 0; j < 7; j++) {
            float nh[7];
            float aeprev = h[j][j];                 // ae[j]
            nh[j] = aeprev + xv[j];                 // pure self-loop at state j
            #pragma unroll
            for (int m = j + 1; m < 7; m++) {
                const float aem = fmaxf(h[j][m], h[j][m - 1] + e[m - 1]);
                nh[m] = fmaxf(aeprev + xv[7 + m - 1], aem + xv[m]);
                aeprev = aem;
            }
            smax[j] = fmaxf(smax[j], nh[6]);
            #pragma unroll
            for (int m = j; m < 7; m++) h[j][m] = nh[m];
        }
        // const column (exact reference semantics incl. restart)
        {
            float ae[7];
            ae[0] = fmaxf(h[7][0], NEG);
            #pragma unroll
            for (int m = 1; m < 7; m++) ae[m] = fmaxf(h[7][m], h[7][m - 1] + e[m - 1]);
            float nh[7];
            nh[0] = fmaxf(0.0f, ae[0] + xv[0]);
            #pragma unroll
            for (int m = 1; m < 7; m++)
                nh[m] = fmaxf(ae[m - 1] + xv[7 + m - 1], ae[m] + xv[m]);
            smax[7] = fmaxf(smax[7], nh[6]);
            #pragma unroll
            for (int m = 0; m < 7; m++) h[7][m] = nh[m];
        }
    }

    float* slot = g_part + ((size_t)(b * Pn + p) * NCH + ch) * 64;
    #pragma unroll
    for (int j = 0; j < 7; j++)
        #pragma unroll
        for (int i = 0; i < 7; i++) slot[j * 7 + i] = (i >= j) ? h[j][i] : NINF;
    #pragma unroll
    for (int i = 0; i < 7; i++) slot[49 + i] = h[7][i];
    #pragma unroll
    for (int j = 0; j < 8; j++) slot[56 + j] = smax[j];
}

// ---------------------------------------------------------------------------
// Fused combine + MLP + log_softmax. One block per batch row.
// ---------------------------------------------------------------------------
__global__ void __launch_bounds__(256)
mlp_kernel(const float* __restrict__ w1, const float* __restrict__ b1,
           const float* __restrict__ w2, const float* __restrict__ b2,
           const float* __restrict__ w3, const float* __restrict__ b3,
           float* __restrict__ out)
{
    const int b = blockIdx.x;
    const int tid = threadIdx.x;
    __shared__ float sc[Pn];
    __shared__ float h1[Hn];
    __shared__ float h2[Hn];

    if (tid < Pn) {
        float h[7];
        h[0] = 0.0f;
        #pragma unroll
        for (int i = 1; i < 7; i++) h[i] = NEG;
        float s = NEG;
        #pragma unroll 1
        for (int c = 0; c < NCH; c++) {
            const float* sl = g_part + ((size_t)(b * Pn + tid) * NCH + c) * 64;
            float ns = fmaxf(s, sl[63]);
            #pragma unroll
            for (int j = 0; j < 7; j++) ns = fmaxf(ns, sl[56 + j] + h[j]);
            float nh[7];
            #pragma unroll
            for (int i = 0; i < 7; i++) {
                float v = sl[49 + i];
                #pragma unroll
                for (int j = 0; j < 7; j++) v = fmaxf(v, sl[j * 7 + i] + h[j]);
                nh[i] = v;
            }
            #pragma unroll
            for (int i = 0; i < 7; i++) h[i] = nh[i];
            s = ns;
        }
        sc[tid] = s;
    }
    __syncthreads();

    if (tid < Hn) {
        float acc = b1[tid];
        #pragma unroll 4
        for (int p = 0; p < Pn; p++) acc = fmaf(sc[p], w1[p * Hn + tid], acc);
        h1[tid] = fmaxf(acc, 0.f);
    }
    __syncthreads();

    if (tid < Hn) {
        float acc = b2[tid];
        #pragma unroll 4
        for (int j = 0; j < Hn; j++) acc = fmaf(h1[j], w2[j * Hn + tid], acc);
        h2[tid] = fmaxf(acc, 0.f);
    }
    __syncthreads();

    if (tid == 0) {
        float l0 = b3[0], l1 = b3[1];
        for (int j = 0; j < Hn; j++) {
            l0 = fmaf(h2[j], w3[j * 2 + 0], l0);
            l1 = fmaf(h2[j], w3[j * 2 + 1], l1);
        }
        float mx  = fmaxf(l0, l1);
        float lse = mx + logf(expf(l0 - mx) + expf(l1 - mx));
        out[b * 2 + 0] = l0 - lse;
        out[b * 2 + 1] = l1 - lse;
    }
}

// ---------------------------------------------------------------------------
extern "C" void kernel_launch(void* const* d_in, const int* in_sizes, int n_in,
                              void* d_out, int out_size)
{
    const int*   docs    = (const int*)  d_in[0];
    const float* emb     = (const float*)d_in[1];
    const float* diags   = (const float*)d_in[2];
    const float* bias    = (const float*)d_in[3];
    const float* epsilon = (const float*)d_in[4];
    const float* w1      = (const float*)d_in[5];
    const float* b1      = (const float*)d_in[6];
    const float* w2      = (const float*)d_in[7];
    const float* b2      = (const float*)d_in[8];
    const float* w3      = (const float*)d_in[9];
    const float* b3      = (const float*)d_in[10];
    float* out = (float*)d_out;

    cudaFuncSetAttribute(gemm_hmma_kernel,
                         cudaFuncAttributeMaxDynamicSharedMemorySize, SMEM_DYN);

    // 0: mark (flags are zero at entry; restored by unmark below)
    dedup_mark_kernel<<<(Mtot + 255) / 256, 256>>>(docs);
    // 1: prefix scan -> g_tok, g_count, flags = uid+1
    dedup_scan_kernel<<<1, 1024>>>();
    // 2: conversions (A gathered via g_tok, B direct)
    conv_all_kernel<<<Mtot + Np, Kp>>>(emb, diags);
    // 3: GEMM (profiled launch index)
    dim3 gridG(Np / TN, Mtot / TM);   // (22, 256); CTAs beyond count exit
    gemm_hmma_kernel<<<gridG, 256, SMEM_DYN>>>(bias);
    // 4: scan (uid lookup inline via flags)
    dim3 gridS(Bn, NCH);              // (64, 4)
    scan_part_kernel<<<gridS, 256>>>(docs, epsilon);
    // 5: fused combine + MLP
    mlp_kernel<<<Bn, 256>>>(w1, b1, w2, b2, w3, b3, out);
    // 6: restore flags to zero for next replay
    dedup_unmark_kernel<<<(Mtot + 255) / 256, 256>>>();
}